// round 2
// baseline (speedup 1.0000x reference)
#include <cuda_runtime.h>

// ============================================================================
// Model_49658411876880: conv->argmax grid, threefry categorical sampling,
// condition LUT (replaces per-call ray march), action histogram, softmax.
//
// RNG reproduces JAX threefry2x32 (jax_threefry_partitionable=True):
//   subkey_i = tf2x32((0,42),(0,i)); bits[i] = y0^y1 of tf2x32(key,(0,i))
// categorical = argmin((-log2 u) * exp(-logits))  [monotone-equivalent]
//
// Pipe balancing: rotl done as IMAD.WIDE (fma pipe) + one fused LOP3 (alu),
// instead of SHF+LOP3 (both alu). Threefry round = IADD + IMAD.WIDE + LOP3.
// ============================================================================

#define H 128
#define W 128
#define NV 16
#define NA 8
#define NP 64
#define NCALLS (H * W * NP)   // 1,048,576

__device__ __align__(16) unsigned char g_grid[H * W];
__device__ int g_first[NV];
__device__ int g_counts[NA];
__device__ unsigned g_keys[12];          // 6 subkeys, (k0,k1) flat
__device__ float g_wexp[66 * 64];        // exp(-logits), field-major [v][p]
__device__ unsigned g_lut[32768 / 32];   // cond bitmask over (obj,pos,neg,dir)

__constant__ int c_dr[8] = { 1, 0, -1, 0, 1, -1, 1, -1 };
__constant__ int c_dc[8] = { 0, 1, 0, -1, 1, 1, -1, -1 };

// rotate-left via wide multiply: lo|hi of x * 2^R. IMAD.WIDE -> fma pipe.
// Inline PTX so ptxas cannot strength-reduce the mul back into shifts.
__device__ __forceinline__ unsigned rotw(unsigned x, unsigned pw) {
    unsigned long long t;
    asm("mul.wide.u32 %0, %1, %2;" : "=l"(t) : "r"(x), "r"(pw));
    return (unsigned)t | (unsigned)(t >> 32);
}

#define TFR(R) { x0 += x1; x1 = rotw(x1, 1u << (R)) ^ x0; }

__device__ __forceinline__ void tf2x32(unsigned ka, unsigned kb,
                                       unsigned x1in,
                                       unsigned &y0, unsigned &y1) {
    unsigned kc = ka ^ kb ^ 0x1BD11BDAu;
    unsigned x0 = ka;            // x0in = 0
    unsigned x1 = x1in + kb;
    TFR(13) TFR(15) TFR(26) TFR(6)
    x0 += kb; x1 += kc + 1u;
    TFR(17) TFR(29) TFR(16) TFR(24)
    x0 += kc; x1 += ka + 2u;
    TFR(13) TFR(15) TFR(26) TFR(6)
    x0 += ka; x1 += kb + 3u;
    TFR(17) TFR(29) TFR(16) TFR(24)
    x0 += kb; x1 += kc + 4u;
    TFR(13) TFR(15) TFR(26) TFR(6)
    x0 += kc; x1 += ka + 5u;
    y0 = x0; y1 = x1;
}

// bits -> u in [tiny,1) exactly as jax.random.uniform(f32); key = -log2(u).
// bits>>9 computed as hi of bits*2^23 (fma pipe).
__device__ __forceinline__ float gkey(unsigned bits) {
    unsigned long long t;
    asm("mul.wide.u32 %0, %1, %2;" : "=l"(t) : "r"(bits), "r"(1u << 23));
    float f = __uint_as_float((unsigned)(t >> 32) | 0x3f800000u) - 1.0f;
    f = fmaxf(f, 1.17549435e-38f);
    return -__log2f(f);
}

template <int VF>
__device__ __forceinline__ int sample1(unsigned ka, unsigned kb, unsigned base,
                                       const float* __restrict__ w) {
    float best = 3.4e38f;
    int bi = 0;
#pragma unroll
    for (int v = 0; v < VF; v++) {
        unsigned y0, y1;
        tf2x32(ka, kb, base + (unsigned)v, y0, y1);
        float a = gkey(y0 ^ y1) * w[v << 6];
        if (a < best) { best = a; bi = v; }
    }
    return bi;
}

// ---------------------------------------------------------------------------
// Kernel 1: subkeys, exp(-logits) tables, init first/counts
// ---------------------------------------------------------------------------
__global__ void k_setup(const float* __restrict__ w_obj,
                        const float* __restrict__ w_pos,
                        const float* __restrict__ w_neg,
                        const float* __restrict__ w_act,
                        const float* __restrict__ w_dir,
                        const float* __restrict__ w_not) {
    int tid = threadIdx.x;
    int nt = blockDim.x;
    if (tid < 6) {
        unsigned y0, y1;
        tf2x32(0u, 42u, (unsigned)tid, y0, y1);
        g_keys[2 * tid]     = y0;
        g_keys[2 * tid + 1] = y1;
    }
    if (tid < NV) g_first[tid] = 1 << 30;
    if (tid >= 32 && tid < 32 + NA) g_counts[tid - 32] = 0;

    for (int e = tid; e < 1024; e += nt) { int v = e >> 6, p = e & 63; g_wexp[e]        = expf(-w_obj[p * 16 + v]); }
    for (int e = tid; e < 1024; e += nt) { int v = e >> 6, p = e & 63; g_wexp[1024 + e] = expf(-w_pos[p * 16 + v]); }
    for (int e = tid; e < 1024; e += nt) { int v = e >> 6, p = e & 63; g_wexp[2048 + e] = expf(-w_neg[p * 16 + v]); }
    for (int e = tid; e < 512;  e += nt) { int v = e >> 6, p = e & 63; g_wexp[3072 + e] = expf(-w_act[p * 8 + v]); }
    for (int e = tid; e < 512;  e += nt) { int v = e >> 6, p = e & 63; g_wexp[3584 + e] = expf(-w_dir[p * 8 + v]); }
    for (int e = tid; e < 128;  e += nt) { int v = e >> 6, p = e & 63; g_wexp[4096 + e] = expf(-w_not[p * 2 + v]); }
}

// ---------------------------------------------------------------------------
// Kernel 2: 3x3 SAME conv + bias, argmax over 16 channels, first occurrence.
// ---------------------------------------------------------------------------
__global__ void __launch_bounds__(256) k_conv(const float* __restrict__ obs,
                                              const float* __restrict__ cw,
                                              const float* __restrict__ cb) {
    __shared__ float sw[NV * 27];
    __shared__ float sb[NV];
    int tid = threadIdx.x;
    for (int i = tid; i < NV * 27; i += 256) sw[i] = cw[i];
    if (tid < NV) sb[tid] = cb[tid];
    __syncthreads();

    int idx = blockIdx.x * 256 + tid;
    int r = idx >> 7, c = idx & 127;

    float patch[27];
#pragma unroll
    for (int ci = 0; ci < 3; ci++)
#pragma unroll
        for (int kr = 0; kr < 3; kr++)
#pragma unroll
            for (int kc = 0; kc < 3; kc++) {
                int rr = r + kr - 1, cc = c + kc - 1;
                bool ok = ((unsigned)rr < 128u) && ((unsigned)cc < 128u);
                patch[ci * 9 + kr * 3 + kc] = ok ? obs[ci * (H * W) + rr * W + cc] : 0.0f;
            }

    float best = -3.4e38f;
    int bi = 0;
#pragma unroll
    for (int v = 0; v < NV; v++) {
        float acc = sb[v];
#pragma unroll
        for (int j = 0; j < 27; j++) acc += patch[j] * sw[v * 27 + j];
        if (acc > best) { best = acc; bi = v; }   // strict > => first max
    }
    g_grid[idx] = (unsigned char)bi;
    atomicMin(&g_first[bi], idx);
}

// ---------------------------------------------------------------------------
// Kernel 3: condition LUT over all (obj,pos,neg,dir) combos -> 4KB bitmask.
// i = ((obj*16+pos)*16+neg)*8+dir ; 32768 combos, one ballot word per 32.
// ---------------------------------------------------------------------------
__global__ void __launch_bounds__(256) k_lut() {
    __shared__ unsigned char s_grid[H * W];
    __shared__ int s_first[NV];
    int tid = threadIdx.x;
    for (int i = tid; i < (H * W) / 16; i += 256)
        ((uint4*)s_grid)[i] = ((const uint4*)g_grid)[i];
    if (tid < NV) s_first[tid] = g_first[tid];
    __syncthreads();

    int i = blockIdx.x * 256 + tid;         // 128 blocks
    int dir =  i        & 7;
    int neg = (i >> 3)  & 15;
    int pos = (i >> 7)  & 15;
    int obj = (i >> 11) & 15;

    int cond = 0;
    int fi = s_first[obj];
    if (fi < H * W) {
        int r = fi >> 7, c = fi & 127;
        int dr = c_dr[dir], dc = c_dc[dir];
#pragma unroll 1
        for (int st = 0; st < 50; st++) {
            r += dr; c += dc;
            if (((unsigned)(r | c)) >= 128u) break;
            int val = s_grid[(r << 7) + c];
            if (val == pos) { cond = 1; break; }
            if (val == neg) break;
        }
    }
    unsigned m = __ballot_sync(0xffffffffu, cond);
    if ((tid & 31) == 0) g_lut[i >> 5] = m;
}

// ---------------------------------------------------------------------------
// Kernel 4: main — 6 categorical samples per call, LUT lookup, histogram.
// ---------------------------------------------------------------------------
__global__ void __launch_bounds__(256) k_main() {
    __shared__ float s_wexp[66 * 64];
    __shared__ unsigned s_lut[1024];
    __shared__ int s_counts[NA];
    __shared__ unsigned s_keys[12];

    int tid = threadIdx.x;
    for (int i = tid; i < 66 * 64; i += 256) s_wexp[i] = g_wexp[i];
    for (int i = tid; i < 1024; i += 256) s_lut[i] = g_lut[i];
    if (tid < 12) s_keys[tid] = g_keys[tid];
    if (tid < NA) s_counts[tid] = 0;
    __syncthreads();

    unsigned n = blockIdx.x * 256u + (unsigned)tid;   // call id
    int p = (int)(n & 63u);
    const float* wp = s_wexp + p;

    int s_obj = sample1<16>(s_keys[0],  s_keys[1],  n * 16u, wp + 0);
    int s_pos = sample1<16>(s_keys[2],  s_keys[3],  n * 16u, wp + 1024);
    int s_neg = sample1<16>(s_keys[4],  s_keys[5],  n * 16u, wp + 2048);
    int s_act = sample1<8> (s_keys[6],  s_keys[7],  n * 8u,  wp + 3072);
    int s_dir = sample1<8> (s_keys[8],  s_keys[9],  n * 8u,  wp + 3584);
    int s_not = sample1<2> (s_keys[10], s_keys[11], n * 2u,  wp + 4096);

    int li = (((((s_obj << 4) | s_pos) << 4) | s_neg) << 3) | s_dir;
    int cond = (int)((s_lut[li >> 5] >> (li & 31)) & 1u);
    cond ^= s_not;

    if (cond) atomicAdd(&s_counts[s_act], 1);
    __syncthreads();
    if (tid < NA) atomicAdd(&g_counts[tid], s_counts[tid]);
}

// ---------------------------------------------------------------------------
// Kernel 5: softmax over 8 action counts
// ---------------------------------------------------------------------------
__global__ void k_final(float* __restrict__ out) {
    if (threadIdx.x == 0) {
        float c[NA], m = -3.4e38f;
#pragma unroll
        for (int i = 0; i < NA; i++) { c[i] = (float)g_counts[i]; m = fmaxf(m, c[i]); }
        float s = 0.0f, e[NA];
#pragma unroll
        for (int i = 0; i < NA; i++) { e[i] = expf(c[i] - m); s += e[i]; }
#pragma unroll
        for (int i = 0; i < NA; i++) out[i] = e[i] / s;
    }
}

// ---------------------------------------------------------------------------
extern "C" void kernel_launch(void* const* d_in, const int* in_sizes, int n_in,
                              void* d_out, int out_size) {
    const float* obs    = (const float*)d_in[0];
    const float* conv_w = (const float*)d_in[1];
    const float* conv_b = (const float*)d_in[2];
    const float* w_obj  = (const float*)d_in[3];
    const float* w_pos  = (const float*)d_in[4];
    const float* w_neg  = (const float*)d_in[5];
    const float* w_act  = (const float*)d_in[6];
    const float* w_dir  = (const float*)d_in[7];
    const float* w_not  = (const float*)d_in[8];

    k_setup<<<1, 256>>>(w_obj, w_pos, w_neg, w_act, w_dir, w_not);
    k_conv<<<(H * W) / 256, 256>>>(obs, conv_w, conv_b);
    k_lut<<<32768 / 256, 256>>>();
    k_main<<<NCALLS / 256, 256>>>();
    k_final<<<1, 32>>>((float*)d_out);
}

// round 3
// speedup vs baseline: 1.2799x; 1.2799x over previous
#include <cuda_runtime.h>

// ============================================================================
// Model_49658411876880: conv->argmax grid, threefry categorical sampling,
// condition LUT, action histogram, softmax.
//
// RNG reproduces JAX threefry2x32 (jax_threefry_partitionable=True):
//   subkey_i = tf2x32((0,42),(0,i)); bits[i] = y0^y1 of tf2x32(key,(0,i))
// categorical = argmin((32 - log2(bits)) * exp(-logits))  [monotone-equiv]
//
// Pipe balancing: SHF+LOP3 stay on alu (unavoidable); ALL integer adds are
// forced onto the fma pipe as IMAD via "x += y * one" with a runtime 1.
// Gumbel key via I2F (cvt pipe) keeps alu lean. Branchless packed argmin.
// ============================================================================

#define H 128
#define W 128
#define NV 16
#define NA 8
#define NP 64
#define NCALLS (H * W * NP)   // 1,048,576

__device__ __align__(16) unsigned char g_grid[H * W];
__device__ int g_first[NV];
__device__ int g_counts[NA];
__device__ unsigned g_keys[48];          // 6 fields x {ka,kb,kc,i1,i2,i3,i4,i5}
__device__ unsigned g_one;               // runtime 1 (defeats const-folding)
__device__ float g_wexp[66 * 64];        // exp(-logits), field-major [v][p]
__device__ unsigned g_lut[32768 / 32];   // cond bitmask over (obj,pos,neg,dir)

__constant__ int c_dr[8] = { 1, 0, -1, 0, 1, -1, 1, -1 };
__constant__ int c_dc[8] = { 0, 1, 0, -1, 1, 1, -1, -1 };

// --- exact threefry for setup (subkey derivation) --------------------------
#define TFR0(R) { x0 += x1; x1 = __funnelshift_l(x1, x1, (R)); x1 ^= x0; }
__device__ __forceinline__ void tf2x32(unsigned ka, unsigned kb, unsigned x1in,
                                       unsigned &y0, unsigned &y1) {
    unsigned kc = ka ^ kb ^ 0x1BD11BDAu;
    unsigned x0 = ka;
    unsigned x1 = x1in + kb;
    TFR0(13) TFR0(15) TFR0(26) TFR0(6)
    x0 += kb; x1 += kc + 1u;
    TFR0(17) TFR0(29) TFR0(16) TFR0(24)
    x0 += kc; x1 += ka + 2u;
    TFR0(13) TFR0(15) TFR0(26) TFR0(6)
    x0 += ka; x1 += kb + 3u;
    TFR0(17) TFR0(29) TFR0(16) TFR0(24)
    x0 += kb; x1 += kc + 4u;
    TFR0(13) TFR0(15) TFR0(26) TFR0(6)
    x0 += kc; x1 += ka + 5u;
    y0 = x0; y1 = x1;
}

// --- main sampling: adds forced to IMAD (fma pipe) via *one ----------------
#define TFR(R) { x0 += x1 * one; x1 = (__funnelshift_l(x1, x1, (R))) ^ x0; }
#define INJ(a, b) { x0 += (a) * one; x1 += (b) * one; }

template <int VF>
__device__ __forceinline__ int sample1(const unsigned* __restrict__ k,
                                       unsigned base,
                                       const float* __restrict__ w,
                                       unsigned one) {
    unsigned ka = k[0], kb = k[1], kc = k[2];
    unsigned i1 = k[3], i2 = k[4], i3 = k[5], i4 = k[6], i5 = k[7];
    unsigned kb0 = kb + base;            // x1 init = kb0 + v
    unsigned best = 0x7FFFFFFFu;
#pragma unroll 4
    for (int v = 0; v < VF; v++) {
        unsigned x0 = ka;
        unsigned x1 = kb0 + (unsigned)v;
        TFR(13) TFR(15) TFR(26) TFR(6)  INJ(kb, i1)
        TFR(17) TFR(29) TFR(16) TFR(24) INJ(kc, i2)
        TFR(13) TFR(15) TFR(26) TFR(6)  INJ(ka, i3)
        TFR(17) TFR(29) TFR(16) TFR(24) INJ(kb, i4)
        TFR(13) TFR(15) TFR(26) TFR(6)  INJ(kc, i5)
        unsigned bits = x0 ^ x1;
        float f = __uint2float_rn(bits);            // I2F (cvt pipe)
        float a = (32.0f - __log2f(f)) * w[v << 6]; // MUFU + FADD + FMUL
        unsigned pk = (__float_as_uint(a) & 0xFFFFFFF0u) | (unsigned)v;
        best = min(best, pk);                       // IMNMX, branchless
    }
    return (int)(best & 15u);
}

// ---------------------------------------------------------------------------
// Kernel 1: subkeys (expanded), exp(-logits) tables, init first/counts
// ---------------------------------------------------------------------------
__global__ void k_setup(const float* __restrict__ w_obj,
                        const float* __restrict__ w_pos,
                        const float* __restrict__ w_neg,
                        const float* __restrict__ w_act,
                        const float* __restrict__ w_dir,
                        const float* __restrict__ w_not) {
    int tid = threadIdx.x;
    int nt = blockDim.x;
    if (tid < 6) {
        unsigned ka, kb;
        tf2x32(0u, 42u, (unsigned)tid, ka, kb);
        unsigned kc = ka ^ kb ^ 0x1BD11BDAu;
        unsigned* o = g_keys + tid * 8;
        o[0] = ka; o[1] = kb; o[2] = kc;
        o[3] = kc + 1u; o[4] = ka + 2u; o[5] = kb + 3u;
        o[6] = kc + 4u; o[7] = ka + 5u;
    }
    if (tid == 6) g_one = 1u;
    if (tid < NV) g_first[tid] = 1 << 30;
    if (tid >= 32 && tid < 32 + NA) g_counts[tid - 32] = 0;

    for (int e = tid; e < 1024; e += nt) { int v = e >> 6, p = e & 63; g_wexp[e]        = expf(-w_obj[p * 16 + v]); }
    for (int e = tid; e < 1024; e += nt) { int v = e >> 6, p = e & 63; g_wexp[1024 + e] = expf(-w_pos[p * 16 + v]); }
    for (int e = tid; e < 1024; e += nt) { int v = e >> 6, p = e & 63; g_wexp[2048 + e] = expf(-w_neg[p * 16 + v]); }
    for (int e = tid; e < 512;  e += nt) { int v = e >> 6, p = e & 63; g_wexp[3072 + e] = expf(-w_act[p * 8 + v]); }
    for (int e = tid; e < 512;  e += nt) { int v = e >> 6, p = e & 63; g_wexp[3584 + e] = expf(-w_dir[p * 8 + v]); }
    for (int e = tid; e < 128;  e += nt) { int v = e >> 6, p = e & 63; g_wexp[4096 + e] = expf(-w_not[p * 2 + v]); }
}

// ---------------------------------------------------------------------------
// Kernel 2: 3x3 SAME conv + bias, argmax over 16 channels, first occurrence.
// ---------------------------------------------------------------------------
__global__ void __launch_bounds__(256) k_conv(const float* __restrict__ obs,
                                              const float* __restrict__ cw,
                                              const float* __restrict__ cb) {
    __shared__ float sw[NV * 27];
    __shared__ float sb[NV];
    int tid = threadIdx.x;
    for (int i = tid; i < NV * 27; i += 256) sw[i] = cw[i];
    if (tid < NV) sb[tid] = cb[tid];
    __syncthreads();

    int idx = blockIdx.x * 256 + tid;
    int r = idx >> 7, c = idx & 127;

    float patch[27];
#pragma unroll
    for (int ci = 0; ci < 3; ci++)
#pragma unroll
        for (int kr = 0; kr < 3; kr++)
#pragma unroll
            for (int kc = 0; kc < 3; kc++) {
                int rr = r + kr - 1, cc = c + kc - 1;
                bool ok = ((unsigned)rr < 128u) && ((unsigned)cc < 128u);
                patch[ci * 9 + kr * 3 + kc] = ok ? obs[ci * (H * W) + rr * W + cc] : 0.0f;
            }

    float best = -3.4e38f;
    int bi = 0;
#pragma unroll
    for (int v = 0; v < NV; v++) {
        float acc = sb[v];
#pragma unroll
        for (int j = 0; j < 27; j++) acc += patch[j] * sw[v * 27 + j];
        if (acc > best) { best = acc; bi = v; }   // strict > => first max
    }
    g_grid[idx] = (unsigned char)bi;
    atomicMin(&g_first[bi], idx);
}

// ---------------------------------------------------------------------------
// Kernel 3: condition LUT over all (obj,pos,neg,dir) combos -> 4KB bitmask.
// ---------------------------------------------------------------------------
__global__ void __launch_bounds__(256) k_lut() {
    __shared__ unsigned char s_grid[H * W];
    __shared__ int s_first[NV];
    int tid = threadIdx.x;
    for (int i = tid; i < (H * W) / 16; i += 256)
        ((uint4*)s_grid)[i] = ((const uint4*)g_grid)[i];
    if (tid < NV) s_first[tid] = g_first[tid];
    __syncthreads();

    int i = blockIdx.x * 256 + tid;         // 128 blocks
    int dir =  i        & 7;
    int neg = (i >> 3)  & 15;
    int pos = (i >> 7)  & 15;
    int obj = (i >> 11) & 15;

    int cond = 0;
    int fi = s_first[obj];
    if (fi < H * W) {
        int r = fi >> 7, c = fi & 127;
        int dr = c_dr[dir], dc = c_dc[dir];
#pragma unroll 1
        for (int st = 0; st < 50; st++) {
            r += dr; c += dc;
            if (((unsigned)(r | c)) >= 128u) break;
            int val = s_grid[(r << 7) + c];
            if (val == pos) { cond = 1; break; }
            if (val == neg) break;
        }
    }
    unsigned m = __ballot_sync(0xffffffffu, cond);
    if ((tid & 31) == 0) g_lut[i >> 5] = m;
}

// ---------------------------------------------------------------------------
// Kernel 4: main — 6 categorical samples per call, LUT lookup, histogram.
// ---------------------------------------------------------------------------
__global__ void __launch_bounds__(256, 4) k_main() {
    __shared__ float s_wexp[66 * 64];
    __shared__ unsigned s_lut[1024];
    __shared__ int s_counts[NA];
    __shared__ unsigned s_keys[48];

    int tid = threadIdx.x;
    for (int i = tid; i < 66 * 64; i += 256) s_wexp[i] = g_wexp[i];
    for (int i = tid; i < 1024; i += 256) s_lut[i] = g_lut[i];
    if (tid < 48) s_keys[tid] = g_keys[tid];
    if (tid < NA) s_counts[tid] = 0;
    __syncthreads();

    unsigned one = g_one;                             // runtime 1 -> IMAD adds
    unsigned n = blockIdx.x * 256u + (unsigned)tid;   // call id
    int p = (int)(n & 63u);
    const float* wp = s_wexp + p;

    int s_obj = sample1<16>(s_keys + 0,  n * 16u, wp + 0,    one);
    int s_pos = sample1<16>(s_keys + 8,  n * 16u, wp + 1024, one);
    int s_neg = sample1<16>(s_keys + 16, n * 16u, wp + 2048, one);
    int s_act = sample1<8> (s_keys + 24, n * 8u,  wp + 3072, one);
    int s_dir = sample1<8> (s_keys + 32, n * 8u,  wp + 3584, one);
    int s_not = sample1<2> (s_keys + 40, n * 2u,  wp + 4096, one);

    int li = (((((s_obj << 4) | s_pos) << 4) | s_neg) << 3) | s_dir;
    int cond = (int)((s_lut[li >> 5] >> (li & 31)) & 1u);
    cond ^= s_not;

    if (cond) atomicAdd(&s_counts[s_act], 1);
    __syncthreads();
    if (tid < NA) atomicAdd(&g_counts[tid], s_counts[tid]);
}

// ---------------------------------------------------------------------------
// Kernel 5: softmax over 8 action counts
// ---------------------------------------------------------------------------
__global__ void k_final(float* __restrict__ out) {
    if (threadIdx.x == 0) {
        float c[NA], m = -3.4e38f;
#pragma unroll
        for (int i = 0; i < NA; i++) { c[i] = (float)g_counts[i]; m = fmaxf(m, c[i]); }
        float s = 0.0f, e[NA];
#pragma unroll
        for (int i = 0; i < NA; i++) { e[i] = expf(c[i] - m); s += e[i]; }
#pragma unroll
        for (int i = 0; i < NA; i++) out[i] = e[i] / s;
    }
}

// ---------------------------------------------------------------------------
extern "C" void kernel_launch(void* const* d_in, const int* in_sizes, int n_in,
                              void* d_out, int out_size) {
    const float* obs    = (const float*)d_in[0];
    const float* conv_w = (const float*)d_in[1];
    const float* conv_b = (const float*)d_in[2];
    const float* w_obj  = (const float*)d_in[3];
    const float* w_pos  = (const float*)d_in[4];
    const float* w_neg  = (const float*)d_in[5];
    const float* w_act  = (const float*)d_in[6];
    const float* w_dir  = (const float*)d_in[7];
    const float* w_not  = (const float*)d_in[8];

    k_setup<<<1, 256>>>(w_obj, w_pos, w_neg, w_act, w_dir, w_not);
    k_conv<<<(H * W) / 256, 256>>>(obs, conv_w, conv_b);
    k_lut<<<32768 / 256, 256>>>();
    k_main<<<NCALLS / 256, 256>>>();
    k_final<<<1, 32>>>((float*)d_out);
}